// round 10
// baseline (speedup 1.0000x reference)
#include <cuda_runtime.h>
#include <cuda_bf16.h>
#include <cuda_fp16.h>

// Problem constants (EdgeConv_33930241638504): N=50000, E=800000, IN=OUT=16, T=8
#define MAXN 50048
#define IN_F 16
#define OUT_F 16
#define T_F 8
#define LN_EPS 1e-5f

// Scratch (device globals: allocation-free rule)
// g fp16, 256B/node, layout [n][j=t/2][o][s=t&1]: half idx = n*128 + j*32 + o*2 + s.
// As uint4[16]: index u -> j = u>>2, output-block ob = u&3; each uint4 holds
// half2s (g[2j,o], g[2j+1,o]) for o = ob*4..ob*4+3.
__device__ __half g_gh[(size_t)MAXN * 128];   // 12.8 MB (L2-resident)
__device__ float  g_c[MAXN * OUT_F];          // c[n][o] fp32 (3.2 MB, L2-resident)
__device__ int    g_idx64;                    // 1 if edge_index int64, 0 if int32

// ---------------------------------------------------------------------------
// Kernel 1: per-node preprocessing (+ inline edge_index dtype detection).
// 16 lanes per node; lane = o. h = relu(LN(x));
//   g[n,t,o] = sum_i h[i]*W[t,i,o]    (fp16, staged via smem -> 1 STG.128/lane)
//   c[n,o]   = sum_i h[i]*b_edge[i,o] (fp32)
//   out[n,o] = sum_i h[i]*root[i,o] + bias[o]
// W/B/R transposed in smem to [t][o][i] (pad 20) -> 4x LDS.128 per dot product.
// ---------------------------------------------------------------------------
#define OPAD 20
__global__ __launch_bounds__(256) void node_kernel(
    const float* __restrict__ x,
    const float* __restrict__ ln_gamma,
    const float* __restrict__ ln_beta,
    const float* __restrict__ w_edge,   // [T, IN*OUT] = 2048 floats
    const float* __restrict__ b_edge,   // [IN*OUT]
    const float* __restrict__ root,     // [IN, OUT]
    const float* __restrict__ bias,     // [OUT]
    const unsigned int* __restrict__ idx_raw,
    float* __restrict__ out,
    int N)
{
    __shared__ float Wt[T_F * IN_F * OPAD];   // [t][o*20 + i]
    __shared__ float Bt[IN_F * OPAD];
    __shared__ float Rt[IN_F * OPAD];
    __shared__ __half Gs[8 * 256];            // 8 warps x (2 nodes x 128 halves)

    for (int idx = threadIdx.x; idx < T_F * IN_F * OUT_F; idx += blockDim.x) {
        int t = idx >> 8, rem = idx & 255, i = rem >> 4, o = rem & 15;
        Wt[t * (IN_F * OPAD) + o * OPAD + i] = w_edge[idx];
    }
    for (int idx = threadIdx.x; idx < IN_F * OUT_F; idx += blockDim.x) {
        int i = idx >> 4, o = idx & 15;
        Bt[o * OPAD + i] = b_edge[idx];
        Rt[o * OPAD + i] = root[idx];
    }

    // dtype detection (block 0, warp 0): int64 LE with values < N => odd words zero.
    if (blockIdx.x == 0 && threadIdx.x < 32) {
        int lane = threadIdx.x;
        unsigned int any = 0;
        #pragma unroll
        for (int k = 0; k < 8; k++) any |= idx_raw[2 * (lane * 8 + k) + 1];
        unsigned int ballot = __ballot_sync(0xffffffffu, any != 0);
        if (lane == 0) g_idx64 = (ballot == 0u) ? 1 : 0;
    }
    __syncthreads();

    int gtid = blockIdx.x * blockDim.x + threadIdx.x;
    int node = gtid >> 4;
    int o    = gtid & 15;
    bool valid = (node < N);
    int n = valid ? node : (N - 1);

    float xv = x[n * IN_F + o];

    // LayerNorm over the 16-lane segment
    float s = xv;
    #pragma unroll
    for (int off = 8; off > 0; off >>= 1) s += __shfl_xor_sync(0xffffffffu, s, off, 16);
    float mu = s * (1.0f / 16.0f);
    float d = xv - mu;
    float v = d * d;
    #pragma unroll
    for (int off = 8; off > 0; off >>= 1) v += __shfl_xor_sync(0xffffffffu, v, off, 16);
    float var = v * (1.0f / 16.0f);
    float rstd = rsqrtf(var + LN_EPS);

    float h_own = d * rstd * ln_gamma[o] + ln_beta[o];
    h_own = fmaxf(h_own, 0.0f);

    // node's h vector as 4 float4s (shuffle-gathered)
    float4 h4[4];
    {
        float hv[IN_F];
        #pragma unroll
        for (int i = 0; i < IN_F; i++) hv[i] = __shfl_sync(0xffffffffu, h_own, i, 16);
        #pragma unroll
        for (int k = 0; k < 4; k++) h4[k] = make_float4(hv[4*k], hv[4*k+1], hv[4*k+2], hv[4*k+3]);
    }

    int warp = threadIdx.x >> 5;
    int lane = threadIdx.x & 31;
    int local_node = (threadIdx.x >> 4) & 1;
    __half* gw = Gs + warp * 256;

    // g: for each t, dot(h, W[t][:,o]) via 4x LDS.128
    #pragma unroll
    for (int t = 0; t < T_F; t++) {
        const float4* wrow = (const float4*)&Wt[t * (IN_F * OPAD) + o * OPAD];
        float acc = 0.0f;
        #pragma unroll
        for (int k = 0; k < 4; k++) {
            float4 w = wrow[k];
            acc = fmaf(h4[k].x, w.x, acc);
            acc = fmaf(h4[k].y, w.y, acc);
            acc = fmaf(h4[k].z, w.z, acc);
            acc = fmaf(h4[k].w, w.w, acc);
        }
        gw[local_node * 128 + (t >> 1) * 32 + o * 2 + (t & 1)] = __float2half(acc);
    }
    __syncwarp();

    // write-out: warp's 2 nodes = 512B = 32 uint4; lane k covers node (k>=16).
    int first_node = blockIdx.x * 16 + warp * 2;
    int covered = first_node + (lane >> 4);
    if (covered < N) {
        uint4 sv = ((const uint4*)gw)[lane];
        ((uint4*)(g_gh + (size_t)first_node * 128))[lane] = sv;
    }

    // c (fp32)
    {
        const float4* brow = (const float4*)&Bt[o * OPAD];
        float acc = 0.0f;
        #pragma unroll
        for (int k = 0; k < 4; k++) {
            float4 w = brow[k];
            acc = fmaf(h4[k].x, w.x, acc);
            acc = fmaf(h4[k].y, w.y, acc);
            acc = fmaf(h4[k].z, w.z, acc);
            acc = fmaf(h4[k].w, w.w, acc);
        }
        if (valid) g_c[n * OUT_F + o] = acc;
    }

    // out init: root transform + bias
    {
        const float4* rrow = (const float4*)&Rt[o * OPAD];
        float acc = bias[o];
        #pragma unroll
        for (int k = 0; k < 4; k++) {
            float4 w = rrow[k];
            acc = fmaf(h4[k].x, w.x, acc);
            acc = fmaf(h4[k].y, w.y, acc);
            acc = fmaf(h4[k].z, w.z, acc);
            acc = fmaf(h4[k].w, w.w, acc);
        }
        if (valid) out[n * OUT_F + o] = acc;
    }
}

// ---------------------------------------------------------------------------
// Kernel 2: per-edge message + scatter, octet-per-edge gather.
// Warp = 8 edges: 4 octets x 2 passes. Octet lane ok loads uint4 ok and ok+8
// of the edge's 256B g-record -> each LDG.128 covers 4 edges x one full 128B
// line (4 wavefronts, optimal). Lane ok holds t in {2j,2j+1} for j=ok>>2 and
// j=2+(ok>>2), outputs ob=ok&3; shfl_xor(4) combines complementary t-halves.
//   msg[o] = c[src,o] + sum_t ea[t]*g[src,t,o];  red.v4 into out[dst].
// ---------------------------------------------------------------------------
__global__ __launch_bounds__(256) void edge_kernel(
    const void* __restrict__ edge_index,       // [2, E] int64 OR int32
    const float* __restrict__ edge_attr,       // [E, 8]
    float* __restrict__ out,
    int E)
{
    int gwarp = (blockIdx.x * blockDim.x + threadIdx.x) >> 5;
    int lane = threadIdx.x & 31;
    int x  = lane >> 3;        // octet 0..3
    int ok = lane & 7;         // lane within octet
    long wbase = (long)gwarp * 8;
    if (wbase >= E) return;

    const uint4*  gp  = (const uint4*)g_gh;    // 16 uint4 per node
    const float4* cp  = (const float4*)g_c;    // 4 float4 per node
    const float4* eap = (const float4*)edge_attr;

    bool sel_hi = (ok >= 4);   // which ea half-set this lane consumes
    int  ob = ok & 3;          // output block

    #pragma unroll
    for (int pass = 0; pass < 2; pass++) {
        long e = wbase + pass * 4 + x;
        bool ev = (e < E);
        long ec = ev ? e : (long)(E - 1);

        int src, dst;
        if (g_idx64) {
            const long long* ei = (const long long*)edge_index;
            src = (int)ei[ec];
            dst = (int)ei[(long)E + ec];
        } else {
            const int* ei = (const int*)edge_index;
            src = ei[ec];
            dst = ei[E + ec];
        }

        // ea: all octet lanes load edge's 8 attrs (broadcast within octet)
        float4 eaA = eap[ec * 2];
        float4 eaB = eap[ec * 2 + 1];
        float a0 = sel_hi ? eaA.z : eaA.x;   // t = 2*j1
        float a1 = sel_hi ? eaA.w : eaA.y;   // t = 2*j1+1
        float a2 = sel_hi ? eaB.z : eaB.x;   // t = 2*j2
        float a3 = sel_hi ? eaB.w : eaB.y;   // t = 2*j2+1

        // g: two full-line loads (uint4 ok and ok+8 of the record)
        uint4 u1 = gp[(size_t)src * 16 + ok];
        uint4 u2 = gp[(size_t)src * 16 + ok + 8];

        float4 p;
        float2 t;
        t = __half22float2(*(const __half2*)&u1.x);
        p.x = fmaf(a0, t.x, a1 * t.y);
        t = __half22float2(*(const __half2*)&u2.x);
        p.x = fmaf(a2, t.x, fmaf(a3, t.y, p.x));
        t = __half22float2(*(const __half2*)&u1.y);
        p.y = fmaf(a0, t.x, a1 * t.y);
        t = __half22float2(*(const __half2*)&u2.y);
        p.y = fmaf(a2, t.x, fmaf(a3, t.y, p.y));
        t = __half22float2(*(const __half2*)&u1.z);
        p.z = fmaf(a0, t.x, a1 * t.y);
        t = __half22float2(*(const __half2*)&u2.z);
        p.z = fmaf(a2, t.x, fmaf(a3, t.y, p.z));
        t = __half22float2(*(const __half2*)&u1.w);
        p.w = fmaf(a0, t.x, a1 * t.y);
        t = __half22float2(*(const __half2*)&u2.w);
        p.w = fmaf(a2, t.x, fmaf(a3, t.y, p.w));

        // combine complementary t-halves (lanes ok and ok^4)
        p.x += __shfl_xor_sync(0xffffffffu, p.x, 4);
        p.y += __shfl_xor_sync(0xffffffffu, p.y, 4);
        p.z += __shfl_xor_sync(0xffffffffu, p.z, 4);
        p.w += __shfl_xor_sync(0xffffffffu, p.w, 4);

        // add c[src, ob*4..ob*4+3]
        float4 c4 = cp[(size_t)src * 4 + ob];
        p.x += c4.x; p.y += c4.y; p.z += c4.z; p.w += c4.w;

        // scatter: lanes ok<4 own distinct (edge, ob) pairs
        if (ev && ok < 4) {
            float* dp = out + (size_t)dst * OUT_F + ob * 4;
            asm volatile("red.global.add.v4.f32 [%0], {%1, %2, %3, %4};"
                         :: "l"(dp), "f"(p.x), "f"(p.y), "f"(p.z), "f"(p.w)
                         : "memory");
        }
    }
}

// ---------------------------------------------------------------------------
extern "C" void kernel_launch(void* const* d_in, const int* in_sizes, int n_in,
                              void* d_out, int out_size)
{
    const float* x        = (const float*)d_in[0];
    const void*  eidx     = d_in[1];
    const float* eattr    = (const float*)d_in[2];
    const float* ln_gamma = (const float*)d_in[3];
    const float* ln_beta  = (const float*)d_in[4];
    const float* w_edge   = (const float*)d_in[5];
    const float* b_edge   = (const float*)d_in[6];
    const float* root     = (const float*)d_in[7];
    const float* bias     = (const float*)d_in[8];
    float* out = (float*)d_out;

    int N = in_sizes[0] / IN_F;
    int E = in_sizes[1] / 2;

    {
        int threads = N * 16;
        int grid = (threads + 255) / 256;
        node_kernel<<<grid, 256>>>(x, ln_gamma, ln_beta, w_edge, b_edge, root, bias,
                                   (const unsigned int*)eidx, out, N);
    }
    {
        // 8 edges per warp, 8 warps per block -> 64 edges per block
        int grid = (E + 63) / 64;
        edge_kernel<<<grid, 256>>>(eidx, eattr, out, E);
    }
}